// round 1
// baseline (speedup 1.0000x reference)
#include <cuda_runtime.h>

#define MAXN 100000
#define HDIM 64

// Scratch buffers (static device globals — no allocation allowed).
// Layout: [2][N][64] contiguous (s-major).
__device__ float g_A1 [2 * MAXN * HDIM];  // layer1 pre-activation (kept: h1 = relu(A1), residual)
__device__ float g_AE1[2 * MAXN * HDIM];  // layer2 pre-activation (kept: e1 = relu(AE1))
__device__ float g_B  [2 * MAXN * HDIM];  // layer3 pre-act, then reused as layer5 pre-act (P)
__device__ float g_C  [2 * MAXN * HDIM];  // layer4 pre-act
__device__ float g_ACT[2 * MAXN * HDIM];  // activated current hidden (GEMM input)
__device__ float g_HW [MAXN * HDIM];      // GEMM output scratch (one edge type at a time)

// ---------------------------------------------------------------------------
// Dense GEMM: out[N,64] = h[N,DIN] @ W[DIN,64]   (fp32)
// 256 threads/block, tile 64 rows x 64 cols, 4x4 register tile per thread.
// W and the h row-tile staged in dynamic shared memory.
// ---------------------------------------------------------------------------
template <int DIN>
__global__ void gemm64_kernel(float* __restrict__ out, const float* __restrict__ h,
                              const float* __restrict__ W, int N) {
    extern __shared__ float smem[];
    float* Ws = smem;              // [DIN][64]
    float* hs = smem + DIN * 64;   // [64][DIN]

    const int tid  = threadIdx.x;
    const int row0 = blockIdx.x * 64;

    // Load W (DIN*64 floats) as float4
    for (int i = tid; i < DIN * 16; i += 256)
        reinterpret_cast<float4*>(Ws)[i] = reinterpret_cast<const float4*>(W)[i];

    // Load h tile [64][DIN] as float4, coalesced
    const int VPR = DIN / 4;  // float4 per row
    for (int i = tid; i < 64 * VPR; i += 256) {
        int r = i / VPR, kc = i % VPR;
        int gr = row0 + r;
        float4 v = make_float4(0.f, 0.f, 0.f, 0.f);
        if (gr < N) v = reinterpret_cast<const float4*>(h)[(size_t)gr * VPR + kc];
        reinterpret_cast<float4*>(hs)[r * VPR + kc] = v;
    }
    __syncthreads();

    const int tx = tid & 15;   // col group: cols 4*tx .. 4*tx+3
    const int ty = tid >> 4;   // row group: rows 4*ty .. 4*ty+3

    float acc[4][4];
#pragma unroll
    for (int i = 0; i < 4; i++)
#pragma unroll
        for (int j = 0; j < 4; j++) acc[i][j] = 0.f;

#pragma unroll 4
    for (int k = 0; k < DIN; k += 4) {
        float4 a[4], b[4];
#pragma unroll
        for (int i = 0; i < 4; i++)
            a[i] = *reinterpret_cast<float4*>(&hs[(ty * 4 + i) * DIN + k]);
#pragma unroll
        for (int kk = 0; kk < 4; kk++)
            b[kk] = *reinterpret_cast<float4*>(&Ws[(k + kk) * 64 + tx * 4]);
#pragma unroll
        for (int i = 0; i < 4; i++) {
            const float* av = reinterpret_cast<const float*>(&a[i]);
#pragma unroll
            for (int kk = 0; kk < 4; kk++) {
                const float* bv = reinterpret_cast<const float*>(&b[kk]);
                acc[i][0] += av[kk] * bv[0];
                acc[i][1] += av[kk] * bv[1];
                acc[i][2] += av[kk] * bv[2];
                acc[i][3] += av[kk] * bv[3];
            }
        }
    }

#pragma unroll
    for (int i = 0; i < 4; i++) {
        int r = row0 + ty * 4 + i;
        if (r < N) {
            float4 v = make_float4(acc[i][0], acc[i][1], acc[i][2], acc[i][3]);
            reinterpret_cast<float4*>(out + (size_t)r * 64 + tx * 4)[0] = v;
        }
    }
}

// ---------------------------------------------------------------------------
// Scatter: out[rows[e]] += vals[e] * hw[cols[e]]  (64 floats per edge)
// 16 threads per edge, each doing one 16-byte vector reduction (red.v4.f32).
// hw and out both L2-resident (25.6 MB each).
// ---------------------------------------------------------------------------
__global__ void scatter_kernel(float* __restrict__ out, const float4* __restrict__ hw,
                               const int* __restrict__ rows, const int* __restrict__ cols,
                               const float* __restrict__ vals, int E) {
    int gid = blockIdx.x * blockDim.x + threadIdx.x;
    int e = gid >> 4;
    if (e >= E) return;
    int c  = gid & 15;
    int r  = __ldg(rows + e);
    int cl = __ldg(cols + e);
    float v = __ldg(vals + e);
    float4 x = hw[(size_t)cl * 16 + c];
    float* dst = out + (size_t)r * 64 + (size_t)c * 4;
    asm volatile("red.global.add.v4.f32 [%0], {%1,%2,%3,%4};"
                 :: "l"(dst), "f"(v * x.x), "f"(v * x.y), "f"(v * x.z), "f"(v * x.w)
                 : "memory");
}

// ---------------------------------------------------------------------------
// Elementwise relu: dst = max(src, 0), over 2*N*64 floats (float4 vectorized)
// ---------------------------------------------------------------------------
__global__ void relu_kernel(float4* __restrict__ dst, const float4* __restrict__ src, int n4) {
    int i = blockIdx.x * blockDim.x + threadIdx.x;
    if (i >= n4) return;
    float4 v = src[i];
    v.x = fmaxf(v.x, 0.f); v.y = fmaxf(v.y, 0.f);
    v.z = fmaxf(v.z, 0.f); v.w = fmaxf(v.w, 0.f);
    dst[i] = v;
}

// ---------------------------------------------------------------------------
// Final: out[s][n] = concat(relu(A1)*att0, relu(AE1)*att1, (P + relu(A1))*att2)
// out shape [2, N, 192]
// ---------------------------------------------------------------------------
__global__ void final_kernel(float* __restrict__ out, const float4* __restrict__ A1,
                             const float4* __restrict__ AE1, const float4* __restrict__ P,
                             const float* __restrict__ att, int N) {
    int gid = blockIdx.x * blockDim.x + threadIdx.x;
    int total = 2 * N * 16;
    if (gid >= total) return;
    int c  = gid & 15;
    int sn = gid >> 4;

    float a0 = __ldg(att + 0), a1 = __ldg(att + 1), a2 = __ldg(att + 2);

    float4 x1 = A1[(size_t)sn * 16 + c];
    x1.x = fmaxf(x1.x, 0.f); x1.y = fmaxf(x1.y, 0.f);
    x1.z = fmaxf(x1.z, 0.f); x1.w = fmaxf(x1.w, 0.f);

    float4 xe = AE1[(size_t)sn * 16 + c];
    xe.x = fmaxf(xe.x, 0.f); xe.y = fmaxf(xe.y, 0.f);
    xe.z = fmaxf(xe.z, 0.f); xe.w = fmaxf(xe.w, 0.f);

    float4 xp = P[(size_t)sn * 16 + c];
    float4 emb = make_float4(xp.x + x1.x, xp.y + x1.y, xp.z + x1.z, xp.w + x1.w);

    float* o = out + (size_t)sn * 192 + (size_t)c * 4;  // sn*192 == (s*N+n)*192
    reinterpret_cast<float4*>(o + 0)[0]   = make_float4(x1.x * a0, x1.y * a0, x1.z * a0, x1.w * a0);
    reinterpret_cast<float4*>(o + 64)[0]  = make_float4(xe.x * a1, xe.y * a1, xe.z * a1, xe.w * a1);
    reinterpret_cast<float4*>(o + 128)[0] = make_float4(emb.x * a2, emb.y * a2, emb.z * a2, emb.w * a2);
}

// ---------------------------------------------------------------------------
// Host launcher
// ---------------------------------------------------------------------------
extern "C" void kernel_launch(void* const* d_in, const int* in_sizes, int n_in,
                              void* d_out, int out_size) {
    const float* feat0 = (const float*)d_in[0];
    const float* feat1 = (const float*)d_in[1];
    const int*   rows  = (const int*)  d_in[2];
    const int*   cols  = (const int*)  d_in[3];
    const float* vals  = (const float*)d_in[4];
    const float* Wl[5] = {(const float*)d_in[5], (const float*)d_in[6], (const float*)d_in[7],
                          (const float*)d_in[8], (const float*)d_in[9]};
    const float* att   = (const float*)d_in[10];
    float* out = (float*)d_out;

    const int N = in_sizes[0] / 128;   // 100000
    const int E = in_sizes[2] / 4;     // 1000000

    float *A1, *AE1, *B, *C, *ACT, *HW;
    cudaGetSymbolAddress((void**)&A1,  g_A1);
    cudaGetSymbolAddress((void**)&AE1, g_AE1);
    cudaGetSymbolAddress((void**)&B,   g_B);
    cudaGetSymbolAddress((void**)&C,   g_C);
    cudaGetSymbolAddress((void**)&ACT, g_ACT);
    cudaGetSymbolAddress((void**)&HW,  g_HW);

    cudaFuncSetAttribute(gemm64_kernel<128>, cudaFuncAttributeMaxDynamicSharedMemorySize, 65536);
    cudaFuncSetAttribute(gemm64_kernel<64>,  cudaFuncAttributeMaxDynamicSharedMemorySize, 32768);

    const int gblocks = (N + 63) / 64;
    const int sblocks = (E * 16 + 255) / 256;
    const int n4      = 2 * N * 16;             // float4 count of a [2][N][64] buffer
    const int rblocks = (n4 + 255) / 256;
    const size_t bufbytes = (size_t)2 * N * 64 * sizeof(float);

    // One heterogeneous GCN layer: for t=(i,j): dst[i] += A_t @ (src[j] @ W[t])
    auto run_layer = [&](const float* src0, const float* src1, const float* W,
                         int din, float* dst) {
        cudaMemsetAsync(dst, 0, bufbytes);
        for (int t = 0; t < 4; t++) {
            const float* src = (t & 1) ? src1 : src0;
            const float* Wt  = W + (size_t)t * din * 64;
            if (din == 128)
                gemm64_kernel<128><<<gblocks, 256, (128*64 + 64*128) * sizeof(float)>>>(HW, src, Wt, N);
            else
                gemm64_kernel<64><<<gblocks, 256, (64*64 + 64*64) * sizeof(float)>>>(HW, src, Wt, N);
            float* d = dst + (size_t)(t >> 1) * N * 64;
            scatter_kernel<<<sblocks, 256>>>(d, (const float4*)HW,
                                             rows + (size_t)t * E, cols + (size_t)t * E,
                                             vals + (size_t)t * E, E);
        }
    };

    // Layer 1: feat (din=128) -> A1
    run_layer(feat0, feat1, Wl[0], 128, A1);
    relu_kernel<<<rblocks, 256>>>((float4*)ACT, (const float4*)A1, n4);
    // Layer 2 -> AE1
    run_layer(ACT, ACT + (size_t)N * 64, Wl[1], 64, AE1);
    relu_kernel<<<rblocks, 256>>>((float4*)ACT, (const float4*)AE1, n4);
    // Layer 3 -> B
    run_layer(ACT, ACT + (size_t)N * 64, Wl[2], 64, B);
    relu_kernel<<<rblocks, 256>>>((float4*)ACT, (const float4*)B, n4);
    // Layer 4 -> C
    run_layer(ACT, ACT + (size_t)N * 64, Wl[3], 64, C);
    relu_kernel<<<rblocks, 256>>>((float4*)ACT, (const float4*)C, n4);
    // Layer 5 -> B (reused as P, no relu)
    run_layer(ACT, ACT + (size_t)N * 64, Wl[4], 64, B);

    // Final: concat(h1*att0, e1*att1, (P + h1)*att2)
    final_kernel<<<rblocks, 256>>>(out, (const float4*)A1, (const float4*)AE1,
                                   (const float4*)B, att, N);
}

// round 2
// speedup vs baseline: 1.4582x; 1.4582x over previous
#include <cuda_runtime.h>

#define MAXN 100000
#define MAXE 1000000
#define HDIM 64

// ---------------------------------------------------------------------------
// Static device scratch (no allocation allowed)
// ---------------------------------------------------------------------------
__device__ float g_A1 [2 * MAXN * HDIM];   // layer1 pre-act (h1 = relu(A1); residual)
__device__ float g_AE1[2 * MAXN * HDIM];   // layer2 pre-act (e1 = relu(AE1))
__device__ float g_B  [2 * MAXN * HDIM];   // layer3 pre-act, reused for layer5 (P)
__device__ float g_C  [2 * MAXN * HDIM];   // layer4 pre-act
__device__ float g_HW [4 * MAXN * HDIM];   // 4 GEMM output buffers (one per edge type)
__device__ int   g_cnt   [4 * MAXN];       // per-type row histogram
__device__ int   g_rowptr[4 * (MAXN + 1)]; // CSR row pointers
__device__ int   g_rowofs[4 * MAXN];       // running fill offsets
__device__ int2  g_cv    [4 * MAXE];       // packed (col, val_bits)
__device__ int   g_part  [4 * 512];        // scan partials

// ---------------------------------------------------------------------------
// CSR build: histogram
// ---------------------------------------------------------------------------
__global__ void hist_kernel(int* __restrict__ cnt, const int* __restrict__ rows,
                            int E, int N) {
    int i = blockIdx.x * blockDim.x + threadIdx.x;
    if (i >= 4 * E) return;
    int t = i / E;
    atomicAdd(&cnt[t * N + __ldg(rows + i)], 1);
}

// 3-phase exclusive scan over cnt[N] per type
__global__ void scan_phase1(const int* __restrict__ cnt, int* __restrict__ part,
                            int N, int nb) {
    int t = blockIdx.y, b = blockIdx.x;
    int i = b * 256 + threadIdx.x;
    int v = (i < N) ? cnt[t * N + i] : 0;
#pragma unroll
    for (int o = 16; o; o >>= 1) v += __shfl_down_sync(0xffffffffu, v, o);
    __shared__ int ws[8];
    if ((threadIdx.x & 31) == 0) ws[threadIdx.x >> 5] = v;
    __syncthreads();
    if (threadIdx.x == 0) {
        int s = 0;
#pragma unroll
        for (int j = 0; j < 8; j++) s += ws[j];
        part[t * nb + b] = s;
    }
}

__global__ void scan_phase2(int* __restrict__ part, int* __restrict__ rowptr,
                            int nb, int N, int E) {
    int t = threadIdx.x;
    if (t >= 4) return;
    int s = 0;
    for (int b = 0; b < nb; b++) {
        int v = part[t * nb + b];
        part[t * nb + b] = s;
        s += v;
    }
    rowptr[t * (N + 1) + N] = E;  // total edge count per type
}

__global__ void scan_phase3(const int* __restrict__ cnt, const int* __restrict__ part,
                            int* __restrict__ rowptr, int* __restrict__ rowofs,
                            int N, int nb) {
    int t = blockIdx.y, b = blockIdx.x;
    int i = b * 256 + threadIdx.x;
    int v = (i < N) ? cnt[t * N + i] : 0;
    __shared__ int sm[256];
    sm[threadIdx.x] = v;
    __syncthreads();
#pragma unroll
    for (int o = 1; o < 256; o <<= 1) {
        int x = (threadIdx.x >= o) ? sm[threadIdx.x - o] : 0;
        __syncthreads();
        sm[threadIdx.x] += x;
        __syncthreads();
    }
    if (i < N) {
        int excl = sm[threadIdx.x] - v + part[t * nb + b];
        rowptr[t * (N + 1) + i] = excl;
        rowofs[t * N + i] = excl;
    }
}

__global__ void fill_kernel(int2* __restrict__ cv, int* __restrict__ rowofs,
                            const int* __restrict__ rows, const int* __restrict__ cols,
                            const float* __restrict__ vals, int E, int N) {
    int i = blockIdx.x * blockDim.x + threadIdx.x;
    if (i >= 4 * E) return;
    int t = i / E;
    int r = __ldg(rows + i);
    int pos = atomicAdd(&rowofs[t * N + r], 1);
    cv[(size_t)t * E + pos] = make_int2(__ldg(cols + i), __float_as_int(__ldg(vals + i)));
}

// ---------------------------------------------------------------------------
// Dense GEMM: out[N,64] = act(h)[N,DIN] @ W[DIN,64], optional relu on load
// ---------------------------------------------------------------------------
template <int DIN, bool RELU>
__global__ void gemm64_kernel(float* __restrict__ out, const float* __restrict__ h,
                              const float* __restrict__ W, int N) {
    extern __shared__ float smem[];
    float* Ws = smem;              // [DIN][64]
    float* hs = smem + DIN * 64;   // [64][DIN]

    const int tid  = threadIdx.x;
    const int row0 = blockIdx.x * 64;

    for (int i = tid; i < DIN * 16; i += 256)
        reinterpret_cast<float4*>(Ws)[i] = reinterpret_cast<const float4*>(W)[i];

    const int VPR = DIN / 4;
    for (int i = tid; i < 64 * VPR; i += 256) {
        int r = i / VPR, kc = i % VPR;
        int gr = row0 + r;
        float4 v = make_float4(0.f, 0.f, 0.f, 0.f);
        if (gr < N) v = reinterpret_cast<const float4*>(h)[(size_t)gr * VPR + kc];
        if (RELU) {
            v.x = fmaxf(v.x, 0.f); v.y = fmaxf(v.y, 0.f);
            v.z = fmaxf(v.z, 0.f); v.w = fmaxf(v.w, 0.f);
        }
        reinterpret_cast<float4*>(hs)[r * VPR + kc] = v;
    }
    __syncthreads();

    const int tx = tid & 15;
    const int ty = tid >> 4;

    float acc[4][4];
#pragma unroll
    for (int i = 0; i < 4; i++)
#pragma unroll
        for (int j = 0; j < 4; j++) acc[i][j] = 0.f;

#pragma unroll 4
    for (int k = 0; k < DIN; k += 4) {
        float4 a[4], b[4];
#pragma unroll
        for (int i = 0; i < 4; i++)
            a[i] = *reinterpret_cast<float4*>(&hs[(ty * 4 + i) * DIN + k]);
#pragma unroll
        for (int kk = 0; kk < 4; kk++)
            b[kk] = *reinterpret_cast<float4*>(&Ws[(k + kk) * 64 + tx * 4]);
#pragma unroll
        for (int i = 0; i < 4; i++) {
            const float* av = reinterpret_cast<const float*>(&a[i]);
#pragma unroll
            for (int kk = 0; kk < 4; kk++) {
                const float* bv = reinterpret_cast<const float*>(&b[kk]);
                acc[i][0] = fmaf(av[kk], bv[0], acc[i][0]);
                acc[i][1] = fmaf(av[kk], bv[1], acc[i][1]);
                acc[i][2] = fmaf(av[kk], bv[2], acc[i][2]);
                acc[i][3] = fmaf(av[kk], bv[3], acc[i][3]);
            }
        }
    }

#pragma unroll
    for (int i = 0; i < 4; i++) {
        int r = row0 + ty * 4 + i;
        if (r < N) {
            float4 v = make_float4(acc[i][0], acc[i][1], acc[i][2], acc[i][3]);
            reinterpret_cast<float4*>(out + (size_t)r * 64 + tx * 4)[0] = v;
        }
    }
}

// ---------------------------------------------------------------------------
// CSR aggregation, two edge types fused into one output (written once):
//   out[r] = sum_{e in csr0[r]} v0_e * hw0[col0_e] + sum_{e in csr1[r]} v1_e * hw1[col1_e]
// 16 lanes per row, each owning one float4 (16B) of the 64-float row.
// ---------------------------------------------------------------------------
__device__ __forceinline__ void fma4(float4& acc, float v, const float4& x) {
    acc.x = fmaf(v, x.x, acc.x);
    acc.y = fmaf(v, x.y, acc.y);
    acc.z = fmaf(v, x.z, acc.z);
    acc.w = fmaf(v, x.w, acc.w);
}

__device__ __forceinline__ void agg_one(float4& acc, const float4* __restrict__ hw,
                                        const int* __restrict__ rp,
                                        const int2* __restrict__ cv, int r, int c) {
    int b = __ldg(rp + r);
    int e = __ldg(rp + r + 1);
    while (b + 2 <= e) {
        int2 p0 = __ldg(cv + b);
        int2 p1 = __ldg(cv + b + 1);
        float4 x0 = __ldg(hw + (size_t)p0.x * 16 + c);
        float4 x1 = __ldg(hw + (size_t)p1.x * 16 + c);
        fma4(acc, __int_as_float(p0.y), x0);
        fma4(acc, __int_as_float(p1.y), x1);
        b += 2;
    }
    if (b < e) {
        int2 p = __ldg(cv + b);
        float4 x = __ldg(hw + (size_t)p.x * 16 + c);
        fma4(acc, __int_as_float(p.y), x);
    }
}

__global__ __launch_bounds__(256) void agg2_kernel(
    float4* __restrict__ out,
    const float4* __restrict__ hw0, const float4* __restrict__ hw1,
    const int* __restrict__ rp0, const int2* __restrict__ cv0,
    const int* __restrict__ rp1, const int2* __restrict__ cv1, int N) {
    int gid = blockIdx.x * blockDim.x + threadIdx.x;
    int r = gid >> 4, c = gid & 15;
    if (r >= N) return;
    float4 acc = make_float4(0.f, 0.f, 0.f, 0.f);
    agg_one(acc, hw0, rp0, cv0, r, c);
    agg_one(acc, hw1, rp1, cv1, r, c);
    out[(size_t)r * 16 + c] = acc;
}

// ---------------------------------------------------------------------------
// Final: out[s][n] = concat(relu(A1)*att0, relu(AE1)*att1, (P + relu(A1))*att2)
// ---------------------------------------------------------------------------
__global__ void final_kernel(float* __restrict__ out, const float4* __restrict__ A1,
                             const float4* __restrict__ AE1, const float4* __restrict__ P,
                             const float* __restrict__ att, int N) {
    int gid = blockIdx.x * blockDim.x + threadIdx.x;
    int total = 2 * N * 16;
    if (gid >= total) return;
    int c = gid & 15;
    int sn = gid >> 4;

    float a0 = __ldg(att + 0), a1 = __ldg(att + 1), a2 = __ldg(att + 2);

    float4 x1 = A1[(size_t)sn * 16 + c];
    x1.x = fmaxf(x1.x, 0.f); x1.y = fmaxf(x1.y, 0.f);
    x1.z = fmaxf(x1.z, 0.f); x1.w = fmaxf(x1.w, 0.f);

    float4 xe = AE1[(size_t)sn * 16 + c];
    xe.x = fmaxf(xe.x, 0.f); xe.y = fmaxf(xe.y, 0.f);
    xe.z = fmaxf(xe.z, 0.f); xe.w = fmaxf(xe.w, 0.f);

    float4 xp = P[(size_t)sn * 16 + c];
    float4 emb = make_float4(xp.x + x1.x, xp.y + x1.y, xp.z + x1.z, xp.w + x1.w);

    float* o = out + (size_t)sn * 192 + (size_t)c * 4;
    reinterpret_cast<float4*>(o + 0)[0]   = make_float4(x1.x * a0, x1.y * a0, x1.z * a0, x1.w * a0);
    reinterpret_cast<float4*>(o + 64)[0]  = make_float4(xe.x * a1, xe.y * a1, xe.z * a1, xe.w * a1);
    reinterpret_cast<float4*>(o + 128)[0] = make_float4(emb.x * a2, emb.y * a2, emb.z * a2, emb.w * a2);
}

// ---------------------------------------------------------------------------
// Host launcher
// ---------------------------------------------------------------------------
extern "C" void kernel_launch(void* const* d_in, const int* in_sizes, int n_in,
                              void* d_out, int out_size) {
    const float* feat0 = (const float*)d_in[0];
    const float* feat1 = (const float*)d_in[1];
    const int*   rows  = (const int*)  d_in[2];
    const int*   cols  = (const int*)  d_in[3];
    const float* vals  = (const float*)d_in[4];
    const float* Wl[5] = {(const float*)d_in[5], (const float*)d_in[6], (const float*)d_in[7],
                          (const float*)d_in[8], (const float*)d_in[9]};
    const float* att   = (const float*)d_in[10];
    float* out = (float*)d_out;

    const int N = in_sizes[0] / 128;   // 100000
    const int E = in_sizes[2] / 4;     // 1000000

    float *A1, *AE1, *B, *C, *HW;
    int *cnt, *rowptr, *rowofs, *part;
    int2* cv;
    cudaGetSymbolAddress((void**)&A1,     g_A1);
    cudaGetSymbolAddress((void**)&AE1,    g_AE1);
    cudaGetSymbolAddress((void**)&B,      g_B);
    cudaGetSymbolAddress((void**)&C,      g_C);
    cudaGetSymbolAddress((void**)&HW,     g_HW);
    cudaGetSymbolAddress((void**)&cnt,    g_cnt);
    cudaGetSymbolAddress((void**)&rowptr, g_rowptr);
    cudaGetSymbolAddress((void**)&rowofs, g_rowofs);
    cudaGetSymbolAddress((void**)&cv,     g_cv);
    cudaGetSymbolAddress((void**)&part,   g_part);

    cudaFuncSetAttribute(gemm64_kernel<128, false>, cudaFuncAttributeMaxDynamicSharedMemorySize, 65536);
    cudaFuncSetAttribute(gemm64_kernel<64, true>,   cudaFuncAttributeMaxDynamicSharedMemorySize, 32768);

    // ---- CSR build (once per call, reused by all 5 layers) ----
    const int nb = (N + 255) / 256;
    cudaMemsetAsync(cnt, 0, (size_t)4 * N * sizeof(int));
    {
        int blocks = (4 * E + 255) / 256;
        hist_kernel<<<blocks, 256>>>(cnt, rows, E, N);
        scan_phase1<<<dim3(nb, 4), 256>>>(cnt, part, N, nb);
        scan_phase2<<<1, 32>>>(part, rowptr, nb, N, E);
        scan_phase3<<<dim3(nb, 4), 256>>>(cnt, part, rowptr, rowofs, N, nb);
        fill_kernel<<<blocks, 256>>>(cv, rowofs, rows, cols, vals, E, N);
    }

    const int gblocks = (N + 63) / 64;
    const int ablocks = (N * 16 + 255) / 256;
    const size_t half = (size_t)N * 64;

    auto rp = [&](int t) { return rowptr + (size_t)t * (N + 1); };
    auto cvp = [&](int t) { return cv + (size_t)t * E; };
    auto hw = [&](int t) { return HW + (size_t)t * half; };

    // One layer: 4 GEMMs (one per edge type) + 2 fused aggregations
    auto run_layer = [&](const float* src0, const float* src1, const float* W,
                         bool relu_in, int din, float* dst) {
        for (int t = 0; t < 4; t++) {
            const float* src = (t & 1) ? src1 : src0;
            const float* Wt = W + (size_t)t * din * 64;
            if (din == 128)
                gemm64_kernel<128, false><<<gblocks, 256, (128 * 64 + 64 * 128) * sizeof(float)>>>(hw(t), src, Wt, N);
            else
                gemm64_kernel<64, true><<<gblocks, 256, (64 * 64 + 64 * 64) * sizeof(float)>>>(hw(t), src, Wt, N);
        }
        // out0 <- types 0,1 ; out1 <- types 2,3
        agg2_kernel<<<ablocks, 256>>>((float4*)dst, (const float4*)hw(0), (const float4*)hw(1),
                                      rp(0), cvp(0), rp(1), cvp(1), N);
        agg2_kernel<<<ablocks, 256>>>((float4*)(dst + half), (const float4*)hw(2), (const float4*)hw(3),
                                      rp(2), cvp(2), rp(3), cvp(3), N);
    };

    // Layer 1: inputs feat (din=128, no relu)
    run_layer(feat0, feat1, Wl[0], false, 128, A1);
    // Layer 2: inputs relu(A1)
    run_layer(A1, A1 + half, Wl[1], true, 64, AE1);
    // Layer 3: inputs relu(AE1)
    run_layer(AE1, AE1 + half, Wl[2], true, 64, B);
    // Layer 4: inputs relu(B)
    run_layer(B, B + half, Wl[3], true, 64, C);
    // Layer 5: inputs relu(C) -> P (reuse B, layer3 pre-act dead after layer4 GEMMs)
    run_layer(C, C + half, Wl[4], true, 64, B);

    // Final concat
    final_kernel<<<(2 * N * 16 + 255) / 256, 256>>>(out, (const float4*)A1, (const float4*)AE1,
                                                    (const float4*)B, att, N);
}

// round 7
// speedup vs baseline: 1.7185x; 1.1786x over previous
#include <cuda_runtime.h>
#include <cstdint>

#define MAXN 100000
#define MAXE 1000000
#define HDIM 64

// ---------------------------------------------------------------------------
// Static device scratch (no allocation allowed)
// ---------------------------------------------------------------------------
__device__ float g_A1 [2 * MAXN * HDIM];   // layer1 pre-act (h1 = relu(A1); residual)
__device__ float g_AE1[2 * MAXN * HDIM];   // layer2 pre-act (e1 = relu(AE1))
__device__ float g_B  [2 * MAXN * HDIM];   // layer3 pre-act, reused for layer5 (P)
__device__ float g_C  [2 * MAXN * HDIM];   // layer4 pre-act
__device__ float g_HW [4 * MAXN * HDIM];   // 4 GEMM output buffers (one per edge type)
__device__ int   g_cnt   [4 * MAXN];
__device__ int   g_rowptr[4 * (MAXN + 1)];
__device__ int   g_rowofs[4 * MAXN];
__device__ int2  g_cv    [4 * MAXE];
__device__ int   g_part  [4 * 512];

// ---------------------------------------------------------------------------
// SIMT GEMM: out[N,64] = act(h)[N,DIN] @ W[DIN,64]
// 256 threads/block, tile 128 rows x 64 cols, 8x4 register tile per thread.
// 12 LDS.128 per 128 FFMA per thread-chunk -> FMA-pipe-bound.
// ---------------------------------------------------------------------------
template <int DIN, bool RELU>
__global__ __launch_bounds__(256) void gemm_kernel(
    float* __restrict__ out, const float* __restrict__ h,
    const float* __restrict__ W, int N) {
    extern __shared__ float smem[];
    float* Ws = smem;              // [DIN][64]
    float* hs = smem + DIN * 64;   // [128][DIN]

    const int tid  = threadIdx.x;
    const int row0 = blockIdx.x * 128;

    // Stage W (DIN*64 floats) as float4
    for (int i = tid; i < DIN * 16; i += 256)
        reinterpret_cast<float4*>(Ws)[i] = reinterpret_cast<const float4*>(W)[i];

    // Stage h tile [128][DIN] as float4, coalesced, relu fused
    const int VPR = DIN / 4;
    for (int i = tid; i < 128 * VPR; i += 256) {
        int r = i / VPR, kc = i % VPR;
        int gr = row0 + r;
        float4 v = make_float4(0.f, 0.f, 0.f, 0.f);
        if (gr < N) v = reinterpret_cast<const float4*>(h)[(size_t)gr * VPR + kc];
        if (RELU) {
            v.x = fmaxf(v.x, 0.f); v.y = fmaxf(v.y, 0.f);
            v.z = fmaxf(v.z, 0.f); v.w = fmaxf(v.w, 0.f);
        }
        reinterpret_cast<float4*>(hs)[r * VPR + kc] = v;
    }
    __syncthreads();

    const int tx = tid & 15;   // col group: cols 4*tx..4*tx+3
    const int ty = tid >> 4;   // row group: rows 8*ty..8*ty+7

    float acc[8][4];
#pragma unroll
    for (int i = 0; i < 8; i++)
#pragma unroll
        for (int j = 0; j < 4; j++) acc[i][j] = 0.f;

#pragma unroll 4
    for (int k = 0; k < DIN; k += 4) {
        float4 b[4];
#pragma unroll
        for (int kk = 0; kk < 4; kk++)
            b[kk] = *reinterpret_cast<float4*>(&Ws[(k + kk) * 64 + tx * 4]);
#pragma unroll
        for (int i = 0; i < 8; i++) {
            float4 a = *reinterpret_cast<float4*>(&hs[(ty * 8 + i) * DIN + k]);
            const float* av = reinterpret_cast<const float*>(&a);
#pragma unroll
            for (int kk = 0; kk < 4; kk++) {
                const float* bv = reinterpret_cast<const float*>(&b[kk]);
                acc[i][0] = fmaf(av[kk], bv[0], acc[i][0]);
                acc[i][1] = fmaf(av[kk], bv[1], acc[i][1]);
                acc[i][2] = fmaf(av[kk], bv[2], acc[i][2]);
                acc[i][3] = fmaf(av[kk], bv[3], acc[i][3]);
            }
        }
    }

#pragma unroll
    for (int i = 0; i < 8; i++) {
        int r = row0 + ty * 8 + i;
        if (r < N) {
            float4 v = make_float4(acc[i][0], acc[i][1], acc[i][2], acc[i][3]);
            reinterpret_cast<float4*>(out + (size_t)r * 64 + tx * 4)[0] = v;
        }
    }
}

// ---------------------------------------------------------------------------
// CSR build kernels
// ---------------------------------------------------------------------------
__global__ void hist_kernel(int* __restrict__ cnt, const int* __restrict__ rows,
                            int E, int N) {
    int i = blockIdx.x * blockDim.x + threadIdx.x;
    if (i >= 4 * E) return;
    int t = i / E;
    atomicAdd(&cnt[t * N + __ldg(rows + i)], 1);
}

__global__ void scan_phase1(const int* __restrict__ cnt, int* __restrict__ part,
                            int N, int nb) {
    int t = blockIdx.y, b = blockIdx.x;
    int i = b * 256 + threadIdx.x;
    int v = (i < N) ? cnt[t * N + i] : 0;
#pragma unroll
    for (int o = 16; o; o >>= 1) v += __shfl_down_sync(0xffffffffu, v, o);
    __shared__ int ws[8];
    if ((threadIdx.x & 31) == 0) ws[threadIdx.x >> 5] = v;
    __syncthreads();
    if (threadIdx.x == 0) {
        int s = 0;
#pragma unroll
        for (int j = 0; j < 8; j++) s += ws[j];
        part[t * nb + b] = s;
    }
}

__global__ void scan_phase2(int* __restrict__ part, int* __restrict__ rowptr,
                            int nb, int N, int E) {
    int t = threadIdx.x;
    if (t >= 4) return;
    int s = 0;
    for (int b = 0; b < nb; b++) {
        int v = part[t * nb + b];
        part[t * nb + b] = s;
        s += v;
    }
    rowptr[t * (N + 1) + N] = E;
}

__global__ void scan_phase3(const int* __restrict__ cnt, const int* __restrict__ part,
                            int* __restrict__ rowptr, int* __restrict__ rowofs,
                            int N, int nb) {
    int t = blockIdx.y, b = blockIdx.x;
    int i = b * 256 + threadIdx.x;
    int v = (i < N) ? cnt[t * N + i] : 0;
    __shared__ int sm[256];
    sm[threadIdx.x] = v;
    __syncthreads();
#pragma unroll
    for (int o = 1; o < 256; o <<= 1) {
        int x = (threadIdx.x >= o) ? sm[threadIdx.x - o] : 0;
        __syncthreads();
        sm[threadIdx.x] += x;
        __syncthreads();
    }
    if (i < N) {
        int excl = sm[threadIdx.x] - v + part[t * nb + b];
        rowptr[t * (N + 1) + i] = excl;
        rowofs[t * N + i] = excl;
    }
}

__global__ void fill_kernel(int2* __restrict__ cv, int* __restrict__ rowofs,
                            const int* __restrict__ rows, const int* __restrict__ cols,
                            const float* __restrict__ vals, int E, int N) {
    int i = blockIdx.x * blockDim.x + threadIdx.x;
    if (i >= 4 * E) return;
    int t = i / E;
    int r = __ldg(rows + i);
    int pos = atomicAdd(&rowofs[t * N + r], 1);
    cv[(size_t)t * E + pos] = make_int2(__ldg(cols + i), __float_as_int(__ldg(vals + i)));
}

// ---------------------------------------------------------------------------
// CSR aggregation, two edge types fused per output row (written once)
// ---------------------------------------------------------------------------
__device__ __forceinline__ void fma4(float4& acc, float v, const float4& x) {
    acc.x = fmaf(v, x.x, acc.x);
    acc.y = fmaf(v, x.y, acc.y);
    acc.z = fmaf(v, x.z, acc.z);
    acc.w = fmaf(v, x.w, acc.w);
}

__device__ __forceinline__ void agg_one(float4& acc, const float4* __restrict__ hw,
                                        const int* __restrict__ rp,
                                        const int2* __restrict__ cv, int r, int c) {
    int b = __ldg(rp + r);
    int e = __ldg(rp + r + 1);
    while (b + 2 <= e) {
        int2 p0 = __ldg(cv + b);
        int2 p1 = __ldg(cv + b + 1);
        float4 x0 = __ldg(hw + (size_t)p0.x * 16 + c);
        float4 x1 = __ldg(hw + (size_t)p1.x * 16 + c);
        fma4(acc, __int_as_float(p0.y), x0);
        fma4(acc, __int_as_float(p1.y), x1);
        b += 2;
    }
    if (b < e) {
        int2 p = __ldg(cv + b);
        float4 x = __ldg(hw + (size_t)p.x * 16 + c);
        fma4(acc, __int_as_float(p.y), x);
    }
}

__global__ __launch_bounds__(256) void agg2_kernel(
    float4* __restrict__ out,
    const float4* __restrict__ hw0, const float4* __restrict__ hw1,
    const int* __restrict__ rp0, const int2* __restrict__ cv0,
    const int* __restrict__ rp1, const int2* __restrict__ cv1, int N) {
    int gid = blockIdx.x * blockDim.x + threadIdx.x;
    int r = gid >> 4, c = gid & 15;
    if (r >= N) return;
    float4 acc = make_float4(0.f, 0.f, 0.f, 0.f);
    agg_one(acc, hw0, rp0, cv0, r, c);
    agg_one(acc, hw1, rp1, cv1, r, c);
    out[(size_t)r * 16 + c] = acc;
}

// ---------------------------------------------------------------------------
// Final concat
// ---------------------------------------------------------------------------
__global__ void final_kernel(float* __restrict__ out, const float4* __restrict__ A1,
                             const float4* __restrict__ AE1, const float4* __restrict__ P,
                             const float* __restrict__ att, int N) {
    int gid = blockIdx.x * blockDim.x + threadIdx.x;
    int total = 2 * N * 16;
    if (gid >= total) return;
    int c = gid & 15;
    int sn = gid >> 4;

    float a0 = __ldg(att + 0), a1 = __ldg(att + 1), a2 = __ldg(att + 2);

    float4 x1 = A1[(size_t)sn * 16 + c];
    x1.x = fmaxf(x1.x, 0.f); x1.y = fmaxf(x1.y, 0.f);
    x1.z = fmaxf(x1.z, 0.f); x1.w = fmaxf(x1.w, 0.f);

    float4 xe = AE1[(size_t)sn * 16 + c];
    xe.x = fmaxf(xe.x, 0.f); xe.y = fmaxf(xe.y, 0.f);
    xe.z = fmaxf(xe.z, 0.f); xe.w = fmaxf(xe.w, 0.f);

    float4 xp = P[(size_t)sn * 16 + c];
    float4 emb = make_float4(xp.x + x1.x, xp.y + x1.y, xp.z + x1.z, xp.w + x1.w);

    float* o = out + (size_t)sn * 192 + (size_t)c * 4;
    reinterpret_cast<float4*>(o + 0)[0]   = make_float4(x1.x * a0, x1.y * a0, x1.z * a0, x1.w * a0);
    reinterpret_cast<float4*>(o + 64)[0]  = make_float4(xe.x * a1, xe.y * a1, xe.z * a1, xe.w * a1);
    reinterpret_cast<float4*>(o + 128)[0] = make_float4(emb.x * a2, emb.y * a2, emb.z * a2, emb.w * a2);
}

// ---------------------------------------------------------------------------
// Host launcher — two-stream fork/join pipeline (graph-capture-safe pattern:
// event record on origin stream -> wait on side stream -> join back via event).
// Stream/event objects are created once; they carry no per-call state, and the
// captured work is identical on every call.
// ---------------------------------------------------------------------------
struct PipeCtx {
    cudaStream_t s1;
    cudaEvent_t efork;
    cudaEvent_t e0[5];  // S0's agg01 done (per layer)
    cudaEvent_t e1[5];  // S1's agg23 done (per layer)
    PipeCtx() {
        cudaStreamCreateWithFlags(&s1, cudaStreamNonBlocking);
        cudaEventCreateWithFlags(&efork, cudaEventDisableTiming);
        for (int i = 0; i < 5; i++) {
            cudaEventCreateWithFlags(&e0[i], cudaEventDisableTiming);
            cudaEventCreateWithFlags(&e1[i], cudaEventDisableTiming);
        }
    }
};
static PipeCtx& pipe_ctx() { static PipeCtx c; return c; }

extern "C" void kernel_launch(void* const* d_in, const int* in_sizes, int n_in,
                              void* d_out, int out_size) {
    const float* feat0 = (const float*)d_in[0];
    const float* feat1 = (const float*)d_in[1];
    const int*   rows  = (const int*)  d_in[2];
    const int*   cols  = (const int*)  d_in[3];
    const float* vals  = (const float*)d_in[4];
    const float* Wl[5] = {(const float*)d_in[5], (const float*)d_in[6], (const float*)d_in[7],
                          (const float*)d_in[8], (const float*)d_in[9]};
    const float* att   = (const float*)d_in[10];
    float* out = (float*)d_out;

    const int N = in_sizes[0] / 128;   // 100000
    const int E = in_sizes[2] / 4;     // 1000000

    float *A1, *AE1, *B, *C, *HW;
    int *cnt, *rowptr, *rowofs, *part;
    int2* cv;
    cudaGetSymbolAddress((void**)&A1,     g_A1);
    cudaGetSymbolAddress((void**)&AE1,    g_AE1);
    cudaGetSymbolAddress((void**)&B,      g_B);
    cudaGetSymbolAddress((void**)&C,      g_C);
    cudaGetSymbolAddress((void**)&HW,     g_HW);
    cudaGetSymbolAddress((void**)&cnt,    g_cnt);
    cudaGetSymbolAddress((void**)&rowptr, g_rowptr);
    cudaGetSymbolAddress((void**)&rowofs, g_rowofs);
    cudaGetSymbolAddress((void**)&cv,     g_cv);
    cudaGetSymbolAddress((void**)&part,   g_part);

    const int SMEM64  = (64 * 64 + 128 * 64) * 4;    // 48 KB
    const int SMEM128 = (128 * 64 + 128 * 128) * 4;  // 96 KB
    cudaFuncSetAttribute(gemm_kernel<128, false>, cudaFuncAttributeMaxDynamicSharedMemorySize, SMEM128);
    cudaFuncSetAttribute(gemm_kernel<64, true>,   cudaFuncAttributeMaxDynamicSharedMemorySize, SMEM64);

    PipeCtx& px = pipe_ctx();
    cudaStream_t S0 = 0;        // capture-origin (legacy default) stream
    cudaStream_t S1 = px.s1;

    // ---- CSR build (S0, once per call) ----
    const int nb = (N + 255) / 256;
    cudaMemsetAsync(cnt, 0, (size_t)4 * N * sizeof(int), S0);
    {
        int blocks = (4 * E + 255) / 256;
        hist_kernel<<<blocks, 256, 0, S0>>>(cnt, rows, E, N);
        scan_phase1<<<dim3(nb, 4), 256, 0, S0>>>(cnt, part, N, nb);
        scan_phase2<<<1, 32, 0, S0>>>(part, rowptr, nb, N, E);
        scan_phase3<<<dim3(nb, 4), 256, 0, S0>>>(cnt, part, rowptr, rowofs, N, nb);
        fill_kernel<<<blocks, 256, 0, S0>>>(cv, rowofs, rows, cols, vals, E, N);
    }
    // Fork S1 off S0 (S1 inherits CSR + nothing else pending)
    cudaEventRecord(px.efork, S0);
    cudaStreamWaitEvent(S1, px.efork, 0);

    const int gblocks = (N + 127) / 128;
    const int ablocks = (N * 16 + 255) / 256;
    const size_t half = (size_t)N * 64;

    auto rp  = [&](int t) { return rowptr + (size_t)t * (N + 1); };
    auto cvp = [&](int t) { return cv + (size_t)t * E; };
    auto hw  = [&](int t) { return HW + (size_t)t * half; };

    auto gemm = [&](cudaStream_t s, const float* src, const float* W, int din, float* dst) {
        if (din == 128)
            gemm_kernel<128, false><<<gblocks, 256, SMEM128, s>>>(dst, src, W, N);
        else
            gemm_kernel<64, true><<<gblocks, 256, SMEM64, s>>>(dst, src, W, N);
    };

    // Per layer l with sources (p0, p1) and dest (d0 = dst, d1 = dst + half):
    //   S0: G_t0(p0->hw0), [wait e1[l-1] for p1], G_t1(p1->hw1), A01 -> d0, record e0[l]
    //   S1: G_t3(p1->hw3), [wait e0[l-1] for p0], G_t2(p0->hw2), A23 -> d1, record e1[l]
    auto run_layer = [&](int l, const float* p0, const float* p1, const float* W,
                         int din, float* dst) {
        // ----- S0 chain -----
        gemm(S0, p0, W + (size_t)0 * din * 64, din, hw(0));          // t0: (i=0, j=0)
        if (l > 0) cudaStreamWaitEvent(S0, px.e1[l - 1], 0);         // p1 ready
        gemm(S0, p1, W + (size_t)1 * din * 64, din, hw(1));          // t1: (i=0, j=1)
        agg2_kernel<<<ablocks, 256, 0, S0>>>((float4*)dst,
            (const float4*)hw(0), (const float4*)hw(1), rp(0), cvp(0), rp(1), cvp(1), N);
        cudaEventRecord(px.e0[l], S0);
        // ----- S1 chain -----
        gemm(S1, p1, W + (size_t)3 * din * 64, din, hw(3));          // t3: (i=1, j=1)
        if (l > 0) cudaStreamWaitEvent(S1, px.e0[l - 1], 0);         // p0 ready
        gemm(S1, p0, W + (size_t)2 * din * 64, din, hw(2));          // t2: (i=1, j=0)
        agg2_kernel<<<ablocks, 256, 0, S1>>>((float4*)(dst + half),
            (const float4*)hw(2), (const float4*)hw(3), rp(2), cvp(2), rp(3), cvp(3), N);
        cudaEventRecord(px.e1[l], S1);
    };

    run_layer(0, feat0, feat1,     Wl[0], 128, A1);   // layer 1
    run_layer(1, A1, A1 + half,    Wl[1], 64,  AE1);  // layer 2
    run_layer(2, AE1, AE1 + half,  Wl[2], 64,  B);    // layer 3
    run_layer(3, B, B + half,      Wl[3], 64,  C);    // layer 4
    run_layer(4, C, C + half,      Wl[4], 64,  B);    // layer 5 -> P (reuse B)

    // Join: final needs A01(l4) (S0, in-stream) and A23(l4) (S1, via event)
    cudaStreamWaitEvent(S0, px.e1[4], 0);
    final_kernel<<<(2 * N * 16 + 255) / 256, 256, 0, S0>>>(
        out, (const float4*)A1, (const float4*)AE1, (const float4*)B, att, N);
}